// round 5
// baseline (speedup 1.0000x reference)
#include <cuda_runtime.h>
#include <cuda_bf16.h>
#include <stdint.h>
#include <math.h>

// ---------------- problem constants ----------------
#define BQ 4
#define DQ 768
#define SQ 1569                  // 1 + 8*196
#define TQ (BQ*SQ)               // 6276 tokens
#define HIDQ 3072
#define LQ 12
#define EPSQ 1e-6f
#define SCALEQ 0.125f            // 64^-0.5

// ---------------- scratch (static device globals) ----------------
__device__ float g_xt [(size_t)TQ*DQ];
__device__ float g_qkv[(size_t)TQ*3*DQ];
__device__ float g_res[(size_t)TQ*DQ];
__device__ __nv_bfloat16 g_aH[(size_t)TQ*DQ],   g_aL[(size_t)TQ*DQ];
__device__ __nv_bfloat16 g_hH[(size_t)TQ*HIDQ], g_hL[(size_t)TQ*HIDQ];
__device__ __nv_bfloat16 g_wH[(size_t)HIDQ*DQ], g_wL[(size_t)HIDQ*DQ];

// ---------------- helpers ----------------
__device__ __forceinline__ uint32_t smem_u32(const void* p) {
    uint32_t a;
    asm("{ .reg .u64 t; cvta.to.shared.u64 t, %1; cvt.u32.u64 %0, t; }" : "=r"(a) : "l"(p));
    return a;
}

__device__ __forceinline__ void cpasync16(uint32_t dst, const void* src, int sz) {
    asm volatile("cp.async.cg.shared.global [%0], [%1], 16, %2;"
                 :: "r"(dst), "l"(src), "r"(sz) : "memory");
}
#define CP_COMMIT() asm volatile("cp.async.commit_group;" ::: "memory")
#define CP_WAIT0()  asm volatile("cp.async.wait_group 0;" ::: "memory")

#define LDSMX4(r, addr) \
    asm volatile("ldmatrix.sync.aligned.m8n8.x4.shared.b16 {%0,%1,%2,%3}, [%4];" \
                 : "=r"((r)[0]), "=r"((r)[1]), "=r"((r)[2]), "=r"((r)[3]) : "r"(addr))

__device__ __forceinline__ void mma16816(float* c,
        uint32_t a0, uint32_t a1, uint32_t a2, uint32_t a3,
        uint32_t b0, uint32_t b1) {
    asm volatile(
        "mma.sync.aligned.m16n8k16.row.col.f32.bf16.bf16.f32 "
        "{%0,%1,%2,%3}, {%4,%5,%6,%7}, {%8,%9}, {%0,%1,%2,%3};\n"
        : "+f"(c[0]), "+f"(c[1]), "+f"(c[2]), "+f"(c[3])
        : "r"(a0), "r"(a1), "r"(a2), "r"(a3), "r"(b0), "r"(b1));
}

__device__ __forceinline__ void wsplit(__nv_bfloat16* hi, __nv_bfloat16* lo,
                                       size_t i, float v) {
    __nv_bfloat16 h = __float2bfloat16_rn(v);
    hi[i] = h;
    lo[i] = __float2bfloat16_rn(v - __bfloat162float(h));
}

__device__ __forceinline__ float block_red(float v, int isMax) {
    __shared__ float red[8];
    int lane = threadIdx.x & 31, w = threadIdx.x >> 5;
    #pragma unroll
    for (int o = 16; o; o >>= 1) {
        float t = __shfl_xor_sync(0xffffffffu, v, o);
        v = isMax ? fmaxf(v, t) : (v + t);
    }
    __syncthreads();
    if (lane == 0) red[w] = v;
    __syncthreads();
    float t = red[0];
    #pragma unroll
    for (int i = 1; i < 8; i++) t = isMax ? fmaxf(t, red[i]) : (t + red[i]);
    return t;
}

// ---------------- im2col -> split bf16 ----------------
__global__ void im2col_k(const float* __restrict__ x,
                         __nv_bfloat16* __restrict__ oH, __nv_bfloat16* __restrict__ oL) {
    int idx = blockIdx.x * 256 + threadIdx.x;
    if (idx >= 6272 * 768) return;
    int r = idx / 768, c = idx % 768;
    int bf = r / 196, p = r % 196;
    int ph = p / 14, pw = p % 14;
    int ch = c >> 8, rem = c & 255;
    int i = rem >> 4, j = rem & 15;
    size_t off = (((size_t)bf * 3 + ch) * 224 + ph * 16 + i) * 224 + pw * 16 + j;
    wsplit(oH, oL, idx, x[off]);
}

// ---------------- weight split (vectorized x4) ----------------
__global__ void cvtw_k(const float* __restrict__ w,
                       __nv_bfloat16* __restrict__ oH, __nv_bfloat16* __restrict__ oL, int n4) {
    int idx = blockIdx.x * 256 + threadIdx.x;
    if (idx >= n4) return;
    float4 v = ((const float4*)w)[idx];
    __nv_bfloat16 hb[4], lb[4];
    float vv[4] = {v.x, v.y, v.z, v.w};
    #pragma unroll
    for (int q = 0; q < 4; q++) {
        hb[q] = __float2bfloat16_rn(vv[q]);
        lb[q] = __float2bfloat16_rn(vv[q] - __bfloat162float(hb[q]));
    }
    ((uint2*)oH)[idx] = *(uint2*)hb;
    ((uint2*)oL)[idx] = *(uint2*)lb;
}

// ---------------- assemble tokens ----------------
__global__ void assemble_k(const float* __restrict__ pe,
                           const float* __restrict__ patch_b,
                           const float* __restrict__ cls_tok,
                           const float* __restrict__ pos,
                           const float* __restrict__ temp,
                           float* __restrict__ xt) {
    int idx = blockIdx.x * 256 + threadIdx.x;
    if (idx >= TQ * DQ) return;
    int t = idx / DQ, dd = idx % DQ;
    int b = t / SQ, s = t % SQ;
    float v;
    if (s == 0) {
        v = cls_tok[dd] + pos[dd];
    } else {
        int sp = s - 1, fr = sp / 196, p = sp % 196;
        v = pe[((size_t)(b * 8 + fr) * 196 + p) * 768 + dd] + patch_b[dd]
            + pos[(size_t)(1 + p) * 768 + dd] + temp[(size_t)fr * 768 + dd];
    }
    xt[idx] = v;
}

// ---------------- layernorm -> split bf16 ----------------
__global__ void ln_k(const float* __restrict__ x, const float* __restrict__ sc,
                     const float* __restrict__ bi,
                     __nv_bfloat16* __restrict__ oH, __nv_bfloat16* __restrict__ oL) {
    int row = blockIdx.x, tid = threadIdx.x;
    const float* xr = x + (size_t)row * DQ;
    float r0 = xr[tid], r1 = xr[tid + 256], r2 = xr[tid + 512];
    float mean = block_red(r0 + r1 + r2, 0) * (1.f / 768.f);
    float d0 = r0 - mean, d1 = r1 - mean, d2 = r2 - mean;
    float var = block_red(d0 * d0 + d1 * d1 + d2 * d2, 0) * (1.f / 768.f);
    float inv = rsqrtf(var + EPSQ);
    size_t base = (size_t)row * DQ;
    wsplit(oH, oL, base + tid,       d0 * inv * sc[tid]       + bi[tid]);
    wsplit(oH, oL, base + tid + 256, d1 * inv * sc[tid + 256] + bi[tid + 256]);
    wsplit(oH, oL, base + tid + 512, d2 * inv * sc[tid + 512] + bi[tid + 512]);
}

__global__ void final_ln_k(const float* __restrict__ xt, const float* __restrict__ sc,
                           const float* __restrict__ bi, float* __restrict__ out) {
    int b = blockIdx.x, tid = threadIdx.x;
    const float* xr = xt + (size_t)(b * SQ) * DQ;
    float r0 = xr[tid], r1 = xr[tid + 256], r2 = xr[tid + 512];
    float mean = block_red(r0 + r1 + r2, 0) * (1.f / 768.f);
    float d0 = r0 - mean, d1 = r1 - mean, d2 = r2 - mean;
    float var = block_red(d0 * d0 + d1 * d1 + d2 * d2, 0) * (1.f / 768.f);
    float inv = rsqrtf(var + EPSQ);
    float* yr = out + (size_t)b * DQ;
    yr[tid]       = d0 * inv * sc[tid]       + bi[tid];
    yr[tid + 256] = d1 * inv * sc[tid + 256] + bi[tid + 256];
    yr[tid + 512] = d2 * inv * sc[tid + 512] + bi[tid + 512];
}

// ============== HMMA GEMM v3: ldmatrix + cp.async 2-stage, 2 CTAs/SM ==============
// C[M,N] = A[M,K] @ W[N,K]^T, A/W pre-split hi/lo bf16 in gmem.
// Block 128x128x32, 8 warps (2x4), warp tile 64x32, mma m16n8k16, 3 terms.
#define ROWB 80                     // smem row stride (bytes), 64B data + 16B pad
#define ARRB (128*ROWB)             // 10240 per array
#define STGB (4*ARRB)               // Ah,Al,Bh,Bl per stage = 40960
#define GT_SMEM (2*STGB)            // 81920 -> 2 CTAs/SM

__device__ __forceinline__ void load_stage(uint32_t sbase,
        const __nv_bfloat16* aH, const __nv_bfloat16* aL,
        const __nv_bfloat16* bH, const __nv_bfloat16* bL,
        int bm, int bn, int k0, int M, int K, int tid) {
    int row = tid >> 1;
    int cb = (tid & 1) * 32;           // byte offset in row: 0 or 32
    int ce = (tid & 1) * 16;           // element offset: 0 or 16
    int gmA = bm + row;
    int szA = (gmA < M) ? 16 : 0;
    int gA = (gmA < M) ? gmA : 0;
    const __nv_bfloat16* sa = aH + (size_t)gA * K + k0 + ce;
    const __nv_bfloat16* sl = aL + (size_t)gA * K + k0 + ce;
    const __nv_bfloat16* sb = bH + (size_t)(bn + row) * K + k0 + ce;
    const __nv_bfloat16* sbl= bL + (size_t)(bn + row) * K + k0 + ce;
    uint32_t d = sbase + row * ROWB + cb;
    cpasync16(d,             sa,      szA);
    cpasync16(d + 16,        sa + 8,  szA);
    cpasync16(d + ARRB,      sl,      szA);
    cpasync16(d + ARRB + 16, sl + 8,  szA);
    cpasync16(d + 2*ARRB,      sb,      16);
    cpasync16(d + 2*ARRB + 16, sb + 8,  16);
    cpasync16(d + 3*ARRB,      sbl,     16);
    cpasync16(d + 3*ARRB + 16, sbl + 8, 16);
}

template<int ACT, int OS, int RS>
__global__ void __launch_bounds__(256, 2) gemm_k(
    const __nv_bfloat16* __restrict__ aH, const __nv_bfloat16* __restrict__ aL,
    const __nv_bfloat16* __restrict__ wH, const __nv_bfloat16* __restrict__ wL,
    const float* __restrict__ bias, const float* __restrict__ res,
    float* __restrict__ outF,
    __nv_bfloat16* __restrict__ oH, __nv_bfloat16* __restrict__ oL,
    int M, int N, int K) {
    extern __shared__ char smem[];
    uint32_t sb = smem_u32(smem);
    int tid = threadIdx.x;
    int lane = tid & 31, w = tid >> 5;
    int warpM = w >> 2, warpN = w & 3;       // 2 x 4
    int g = lane >> 2, q = lane & 3;
    int bm = blockIdx.y * 128, bn = blockIdx.x * 128;
    const int nkt = K >> 5;

    float acc[4][4][4];
    #pragma unroll
    for (int i = 0; i < 4; i++)
        #pragma unroll
        for (int j = 0; j < 4; j++)
            #pragma unroll
            for (int c = 0; c < 4; c++) acc[i][j][c] = 0.f;

    // prologue: stage 0
    load_stage(sb, aH, aL, wH, wL, bm, bn, 0, M, K, tid);
    CP_COMMIT();

    int arow = warpM * 64 + (lane & 15);
    int brow = warpN * 32 + (lane & 15);
    int lcol = (lane >> 4) * 16;

    for (int kt = 0; kt < nkt; kt++) {
        int cur = kt & 1;
        CP_WAIT0();                      // fill of buf cur complete
        __syncthreads();                 // all warps done with buf nxt (prev compute)
        if (kt + 1 < nkt) {
            load_stage(sb + (cur ^ 1) * STGB, aH, aL, wH, wL,
                       bm, bn, (kt + 1) << 5, M, K, tid);
            CP_COMMIT();
        }

        uint32_t st = sb + cur * STGB;
        #pragma unroll
        for (int kk = 0; kk < 2; kk++) {
            uint32_t ah[4][4], al[4][4];
            #pragma unroll
            for (int i = 0; i < 4; i++) {
                uint32_t addr = st + (arow + i * 16) * ROWB + kk * 32 + lcol;
                LDSMX4(ah[i], addr);
                LDSMX4(al[i], addr + ARRB);
            }
            #pragma unroll
            for (int jj = 0; jj < 2; jj++) {
                uint32_t bh[4], bl[4];
                uint32_t addr = st + 2 * ARRB + (brow + jj * 16) * ROWB + kk * 32 + lcol;
                LDSMX4(bh, addr);
                LDSMX4(bl, addr + ARRB);
                #pragma unroll
                for (int sel = 0; sel < 2; sel++) {
                    int j = jj * 2 + sel;
                    uint32_t b0h = bh[sel], b1h = bh[sel + 2];
                    uint32_t b0l = bl[sel], b1l = bl[sel + 2];
                    #pragma unroll
                    for (int i = 0; i < 4; i++) {
                        mma16816(acc[i][j], ah[i][0], ah[i][1], ah[i][2], ah[i][3], b0h, b1h);
                        mma16816(acc[i][j], ah[i][0], ah[i][1], ah[i][2], ah[i][3], b0l, b1l);
                        mma16816(acc[i][j], al[i][0], al[i][1], al[i][2], al[i][3], b0h, b1h);
                    }
                }
            }
        }
    }

    // epilogue
    #pragma unroll
    for (int i = 0; i < 4; i++) {
        int m0 = bm + warpM * 64 + i * 16 + g;
        #pragma unroll
        for (int j = 0; j < 4; j++) {
            int n0 = bn + warpN * 32 + j * 8 + q * 2;
            float bx = bias ? bias[n0] : 0.f;
            float by = bias ? bias[n0 + 1] : 0.f;
            #pragma unroll
            for (int half = 0; half < 2; half++) {
                int m = m0 + half * 8;
                if (m >= M) continue;
                float v0 = acc[i][j][half * 2 + 0] + bx;
                float v1 = acc[i][j][half * 2 + 1] + by;
                if (RS) {
                    const float* rp = res + (size_t)m * N + n0;
                    v0 += rp[0]; v1 += rp[1];
                }
                if (ACT) {
                    v0 = 0.5f * v0 * (1.f + erff(v0 * 0.70710678118654752f));
                    v1 = 0.5f * v1 * (1.f + erff(v1 * 0.70710678118654752f));
                }
                if (OS) {
                    __nv_bfloat16 h0 = __float2bfloat16_rn(v0);
                    __nv_bfloat16 h1 = __float2bfloat16_rn(v1);
                    __nv_bfloat16 l0 = __float2bfloat16_rn(v0 - __bfloat162float(h0));
                    __nv_bfloat16 l1 = __float2bfloat16_rn(v1 - __bfloat162float(h1));
                    __nv_bfloat162 hp; hp.x = h0; hp.y = h1;
                    __nv_bfloat162 lp; lp.x = l0; lp.y = l1;
                    *(__nv_bfloat162*)&oH[(size_t)m * N + n0] = hp;
                    *(__nv_bfloat162*)&oL[(size_t)m * N + n0] = lp;
                } else {
                    *(float2*)(outF + (size_t)m * N + n0) = make_float2(v0, v1);
                }
            }
        }
    }
}

// ---------------- cls-row attention (out -> split bf16) ----------------
__global__ void cls_attn_k(const float* __restrict__ qkv,
                           __nv_bfloat16* __restrict__ oH, __nv_bfloat16* __restrict__ oL) {
    __shared__ float sc[SQ];
    __shared__ float qv[64];
    __shared__ float op[256];
    int bh = blockIdx.x, b = bh / 12, h = bh % 12;
    int tid = threadIdx.x;
    size_t base = (size_t)(b * SQ) * 2304 + (size_t)h * 64;
    if (tid < 64) qv[tid] = qkv[base + tid] * SCALEQ;
    __syncthreads();
    float lmax = -1e30f;
    for (int s = tid; s < SQ; s += 256) {
        const float* kp = qkv + (size_t)(b * SQ + s) * 2304 + 768 + h * 64;
        float d = 0.f;
        #pragma unroll
        for (int i = 0; i < 64; i++) d += qv[i] * kp[i];
        sc[s] = d; lmax = fmaxf(lmax, d);
    }
    float mx = block_red(lmax, 1);
    float lsum = 0.f;
    for (int s = tid; s < SQ; s += 256) {
        float e = expf(sc[s] - mx);
        sc[s] = e; lsum += e;
    }
    float den = block_red(lsum, 0);
    __syncthreads();
    int part = tid >> 6, d = tid & 63;
    float acc = 0.f;
    for (int s = part; s < SQ; s += 4)
        acc += sc[s] * qkv[(size_t)(b * SQ + s) * 2304 + 1536 + h * 64 + d];
    op[tid] = acc;
    __syncthreads();
    if (tid < 64) {
        float t = op[tid] + op[tid + 64] + op[tid + 128] + op[tid + 192];
        wsplit(oH, oL, (size_t)(b * SQ) * 768 + h * 64 + tid, t / den);
    }
}

// ---------------- space attention (out -> split bf16) ----------------
#define SPACE_SMEM ((197*65*2 + 8*197 + 8*64) * 4)
__global__ void space_attn_k(const float* __restrict__ qkv,
                             __nv_bfloat16* __restrict__ oH, __nv_bfloat16* __restrict__ oL) {
    extern __shared__ float sm[];
    float* Ks = sm;
    float* Vs = Ks + 197 * 65;
    float* pb = Vs + 197 * 65;
    float* qb = pb + 8 * 197;
    int blk = blockIdx.x;
    int fr = blk % 8, h = (blk / 8) % 12, b = blk / 96;
    int tid = threadIdx.x, lane = tid & 31, w = tid >> 5;
    for (int idx = tid; idx < 197 * 64; idx += 256) {
        int kk = idx >> 6, d = idx & 63;
        int s = kk ? (1 + fr * 196 + kk - 1) : 0;
        size_t o = (size_t)(b * SQ + s) * 2304 + h * 64;
        Ks[kk * 65 + d] = qkv[o + 768 + d];
        Vs[kk * 65 + d] = qkv[o + 1536 + d];
    }
    __syncthreads();
    for (int qi = w; qi < 196; qi += 8) {
        int sq = 1 + fr * 196 + qi;
        size_t oq = (size_t)(b * SQ + sq) * 2304 + h * 64;
        qb[w * 64 + lane]      = qkv[oq + lane] * SCALEQ;
        qb[w * 64 + lane + 32] = qkv[oq + lane + 32] * SCALEQ;
        __syncwarp();
        float ls[7];
        float lmax = -1e30f;
        int cnt = 0;
        for (int kk = lane; kk < 197; kk += 32) {
            float s = 0.f;
            #pragma unroll
            for (int d = 0; d < 64; d++) s += qb[w * 64 + d] * Ks[kk * 65 + d];
            ls[cnt++] = s; lmax = fmaxf(lmax, s);
        }
        #pragma unroll
        for (int o = 16; o; o >>= 1) lmax = fmaxf(lmax, __shfl_xor_sync(0xffffffffu, lmax, o));
        float lsum = 0.f; cnt = 0;
        for (int kk = lane; kk < 197; kk += 32) {
            float e = expf(ls[cnt++] - lmax);
            pb[w * 197 + kk] = e; lsum += e;
        }
        #pragma unroll
        for (int o = 16; o; o >>= 1) lsum += __shfl_xor_sync(0xffffffffu, lsum, o);
        float inv = 1.f / lsum;
        __syncwarp();
        float a0 = 0.f, a1 = 0.f;
        for (int kk = 0; kk < 197; kk++) {
            float p = pb[w * 197 + kk];
            a0 += p * Vs[kk * 65 + lane];
            a1 += p * Vs[kk * 65 + lane + 32];
        }
        size_t oo = (size_t)(b * SQ + sq) * 768 + h * 64;
        wsplit(oH, oL, oo + lane,      a0 * inv);
        wsplit(oH, oL, oo + lane + 32, a1 * inv);
        __syncwarp();
    }
}

// ---------------- time attention (out -> split bf16) ----------------
__global__ void time_attn_k(const float* __restrict__ qkv,
                            __nv_bfloat16* __restrict__ oH, __nv_bfloat16* __restrict__ oL) {
    int g = blockIdx.x * 8 + (threadIdx.x >> 5);
    int lane = threadIdx.x & 31;
    if (g >= 48 * 196) return;
    int bh = g / 196, pos = g % 196;
    int b = bh / 12, h = bh % 12;
    float K0[9], K1[9], V0[9], V1[9];
    #pragma unroll
    for (int kk = 0; kk < 9; kk++) {
        int s = kk ? (1 + (kk - 1) * 196 + pos) : 0;
        size_t o = (size_t)(b * SQ + s) * 2304 + h * 64;
        K0[kk] = qkv[o + 768 + lane];  K1[kk] = qkv[o + 768 + lane + 32];
        V0[kk] = qkv[o + 1536 + lane]; V1[kk] = qkv[o + 1536 + lane + 32];
    }
    for (int fq = 0; fq < 8; fq++) {
        int sq = 1 + fq * 196 + pos;
        size_t oq = (size_t)(b * SQ + sq) * 2304 + h * 64;
        float q0 = qkv[oq + lane] * SCALEQ, q1 = qkv[oq + lane + 32] * SCALEQ;
        float sc[9];
        #pragma unroll
        for (int kk = 0; kk < 9; kk++) {
            float p = q0 * K0[kk] + q1 * K1[kk];
            #pragma unroll
            for (int o = 16; o; o >>= 1) p += __shfl_xor_sync(0xffffffffu, p, o);
            sc[kk] = p;
        }
        float mx = sc[0];
        #pragma unroll
        for (int kk = 1; kk < 9; kk++) mx = fmaxf(mx, sc[kk]);
        float den = 0.f;
        #pragma unroll
        for (int kk = 0; kk < 9; kk++) { sc[kk] = expf(sc[kk] - mx); den += sc[kk]; }
        float inv = 1.f / den;
        float a0 = 0.f, a1 = 0.f;
        #pragma unroll
        for (int kk = 0; kk < 9; kk++) { a0 += sc[kk] * V0[kk]; a1 += sc[kk] * V1[kk]; }
        size_t oo = (size_t)(b * SQ + sq) * 768 + h * 64;
        wsplit(oH, oL, oo + lane,      a0 * inv);
        wsplit(oH, oL, oo + lane + 32, a1 * inv);
    }
}

// ================== host orchestration ==================
// mode: 0 fp32 out, 1 fp32 out + residual, 2 gelu + split-bf16 out
static void gemm(const __nv_bfloat16* aH, const __nv_bfloat16* aL,
                 const __nv_bfloat16* wHp, const __nv_bfloat16* wLp,
                 const float* bias, const float* res,
                 float* outF, __nv_bfloat16* oH, __nv_bfloat16* oL,
                 int M, int N, int K, int mode) {
    dim3 g(N / 128, (M + 127) / 128);
    if (mode == 0)
        gemm_k<0,0,0><<<g, 256, GT_SMEM>>>(aH, aL, wHp, wLp, bias, res, outF, oH, oL, M, N, K);
    else if (mode == 1)
        gemm_k<0,0,1><<<g, 256, GT_SMEM>>>(aH, aL, wHp, wLp, bias, res, outF, oH, oL, M, N, K);
    else
        gemm_k<1,1,0><<<g, 256, GT_SMEM>>>(aH, aL, wHp, wLp, bias, res, outF, oH, oL, M, N, K);
}

extern "C" void kernel_launch(void* const* d_in, const int* in_sizes, int n_in,
                              void* d_out, int out_size) {
    const float* x       = (const float*)d_in[0];
    const float* patch_w = (const float*)d_in[1];
    const float* patch_b = (const float*)d_in[2];
    const float* cls_tok = (const float*)d_in[3];
    const float* pos     = (const float*)d_in[4];
    const float* temp    = (const float*)d_in[5];
    const float* n1s = (const float*)d_in[6],  *n1b = (const float*)d_in[7];
    const float* n2s = (const float*)d_in[8],  *n2b = (const float*)d_in[9];
    const float* n3s = (const float*)d_in[10], *n3b = (const float*)d_in[11];
    const float* aqw = (const float*)d_in[12], *aqb = (const float*)d_in[13];
    const float* apw = (const float*)d_in[14], *apb = (const float*)d_in[15];
    const float* tqw = (const float*)d_in[16], *tqb = (const float*)d_in[17];
    const float* tpw = (const float*)d_in[18], *tpb = (const float*)d_in[19];
    const float* f1w = (const float*)d_in[20], *f1b = (const float*)d_in[21];
    const float* f2w = (const float*)d_in[22], *f2b = (const float*)d_in[23];
    const float* nfs = (const float*)d_in[24], *nfb = (const float*)d_in[25];
    float* out = (float*)d_out;

    float *xt, *qkv, *res;
    __nv_bfloat16 *aH, *aL, *hH, *hL, *wH, *wL;
    cudaGetSymbolAddress((void**)&xt,  g_xt);
    cudaGetSymbolAddress((void**)&qkv, g_qkv);
    cudaGetSymbolAddress((void**)&res, g_res);
    cudaGetSymbolAddress((void**)&aH,  g_aH);
    cudaGetSymbolAddress((void**)&aL,  g_aL);
    cudaGetSymbolAddress((void**)&hH,  g_hH);
    cudaGetSymbolAddress((void**)&hL,  g_hL);
    cudaGetSymbolAddress((void**)&wH,  g_wH);
    cudaGetSymbolAddress((void**)&wL,  g_wL);

    cudaFuncSetAttribute(space_attn_k, cudaFuncAttributeMaxDynamicSharedMemorySize, SPACE_SMEM);
    cudaFuncSetAttribute(gemm_k<0,0,0>, cudaFuncAttributeMaxDynamicSharedMemorySize, GT_SMEM);
    cudaFuncSetAttribute(gemm_k<0,0,1>, cudaFuncAttributeMaxDynamicSharedMemorySize, GT_SMEM);
    cudaFuncSetAttribute(gemm_k<1,1,0>, cudaFuncAttributeMaxDynamicSharedMemorySize, GT_SMEM);

    // ---- patch embedding ----
    im2col_k<<<(6272 * 768 + 255) / 256, 256>>>(x, hH, hL);
    cvtw_k<<<(768 * 768 / 4 + 255) / 256, 256>>>(patch_w, wH, wL, 768 * 768 / 4);
    gemm(hH, hL, wH, wL, nullptr, nullptr, qkv, nullptr, nullptr, 6272, 768, 768, 0);
    assemble_k<<<(TQ * DQ + 255) / 256, 256>>>(qkv, patch_b, cls_tok, pos, temp, xt);

    for (int l = 0; l < LQ; l++) {
        // ---- time attention ----
        ln_k<<<TQ, 256>>>(xt, n3s + (size_t)l * DQ, n3b + (size_t)l * DQ, aH, aL);
        cvtw_k<<<(3 * DQ * DQ / 4 + 255) / 256, 256>>>(tqw + (size_t)l * 3 * DQ * DQ, wH, wL, 3 * DQ * DQ / 4);
        gemm(aH, aL, wH, wL, tqb + (size_t)l * 3 * DQ, nullptr,
             qkv, nullptr, nullptr, TQ, 3 * DQ, DQ, 0);
        cls_attn_k<<<48, 256>>>(qkv, aH, aL);
        time_attn_k<<<1176, 256>>>(qkv, aH, aL);
        cvtw_k<<<(DQ * DQ / 4 + 255) / 256, 256>>>(tpw + (size_t)l * DQ * DQ, wH, wL, DQ * DQ / 4);
        gemm(aH, aL, wH, wL, tpb + (size_t)l * DQ, xt,
             res, nullptr, nullptr, TQ, DQ, DQ, 1);                 // time_res
        // ---- space attention ----
        ln_k<<<TQ, 256>>>(res, n1s + (size_t)l * DQ, n1b + (size_t)l * DQ, aH, aL);
        cvtw_k<<<(3 * DQ * DQ / 4 + 255) / 256, 256>>>(aqw + (size_t)l * 3 * DQ * DQ, wH, wL, 3 * DQ * DQ / 4);
        gemm(aH, aL, wH, wL, aqb + (size_t)l * 3 * DQ, nullptr,
             qkv, nullptr, nullptr, TQ, 3 * DQ, DQ, 0);
        cls_attn_k<<<48, 256>>>(qkv, aH, aL);
        space_attn_k<<<384, 256, SPACE_SMEM>>>(qkv, aH, aL);
        cvtw_k<<<(DQ * DQ / 4 + 255) / 256, 256>>>(apw + (size_t)l * DQ * DQ, wH, wL, DQ * DQ / 4);
        gemm(aH, aL, wH, wL, apb + (size_t)l * DQ, xt,
             res, nullptr, nullptr, TQ, DQ, DQ, 1);                 // space_res
        // ---- MLP ----
        ln_k<<<TQ, 256>>>(res, n2s + (size_t)l * DQ, n2b + (size_t)l * DQ, aH, aL);
        cvtw_k<<<(HIDQ * DQ / 4 + 255) / 256, 256>>>(f1w + (size_t)l * HIDQ * DQ, wH, wL, HIDQ * DQ / 4);
        gemm(aH, aL, wH, wL, f1b + (size_t)l * HIDQ, nullptr,
             nullptr, hH, hL, TQ, HIDQ, DQ, 2);                     // gelu -> split
        cvtw_k<<<(DQ * HIDQ / 4 + 255) / 256, 256>>>(f2w + (size_t)l * DQ * HIDQ, wH, wL, DQ * HIDQ / 4);
        gemm(hH, hL, wH, wL, f2b + (size_t)l * DQ, res,
             xt, nullptr, nullptr, TQ, DQ, HIDQ, 1);                // xt = res + mlp
    }

    final_ln_k<<<BQ, 256>>>(xt, nfs, nfb, out);
}

// round 6
// speedup vs baseline: 1.8451x; 1.8451x over previous
#include <cuda_runtime.h>
#include <cuda_fp16.h>
#include <stdint.h>
#include <math.h>

// ---------------- problem constants ----------------
#define BQ 4
#define DQ 768
#define SQ 1569                  // 1 + 8*196
#define TQ (BQ*SQ)               // 6276 tokens
#define HIDQ 3072
#define LQ 12
#define EPSQ 1e-6f
#define SCALEQ 0.125f            // 64^-0.5

// ---------------- scratch (static device globals) ----------------
__device__ float g_xt  [(size_t)TQ*DQ];
__device__ float g_ln  [(size_t)TQ*DQ];
__device__ float g_qkv [(size_t)TQ*3*DQ];
__device__ float g_attn[(size_t)TQ*DQ];
__device__ float g_res [(size_t)TQ*DQ];
__device__ float g_hid [(size_t)TQ*HIDQ];   // also reused as im2col buffer

// ---------------- block reduce helper (256-thread blocks) ----------------
__device__ __forceinline__ float block_red(float v, int isMax) {
    __shared__ float red[8];
    int lane = threadIdx.x & 31, w = threadIdx.x >> 5;
    #pragma unroll
    for (int o = 16; o; o >>= 1) {
        float t = __shfl_xor_sync(0xffffffffu, v, o);
        v = isMax ? fmaxf(v, t) : (v + t);
    }
    __syncthreads();
    if (lane == 0) red[w] = v;
    __syncthreads();
    float t = red[0];
    #pragma unroll
    for (int i = 1; i < 8; i++) t = isMax ? fmaxf(t, red[i]) : (t + red[i]);
    return t;
}

// ---------------- im2col for patch embedding ----------------
__global__ void im2col_k(const float* __restrict__ x, float* __restrict__ out) {
    int idx = blockIdx.x * 256 + threadIdx.x;
    if (idx >= 6272 * 768) return;
    int r = idx / 768, c = idx % 768;
    int bf = r / 196, p = r % 196;
    int ph = p / 14, pw = p % 14;
    int ch = c >> 8, rem = c & 255;
    int i = rem >> 4, j = rem & 15;
    size_t off = (((size_t)bf * 3 + ch) * 224 + ph * 16 + i) * 224 + pw * 16 + j;
    out[idx] = x[off];
}

// ---------------- assemble tokens ----------------
__global__ void assemble_k(const float* __restrict__ pe,
                           const float* __restrict__ patch_b,
                           const float* __restrict__ cls_tok,
                           const float* __restrict__ pos,
                           const float* __restrict__ temp,
                           float* __restrict__ xt) {
    int idx = blockIdx.x * 256 + threadIdx.x;
    if (idx >= TQ * DQ) return;
    int t = idx / DQ, dd = idx % DQ;
    int b = t / SQ, s = t % SQ;
    float v;
    if (s == 0) {
        v = cls_tok[dd] + pos[dd];
    } else {
        int sp = s - 1, fr = sp / 196, p = sp % 196;
        v = pe[((size_t)(b * 8 + fr) * 196 + p) * 768 + dd] + patch_b[dd]
            + pos[(size_t)(1 + p) * 768 + dd] + temp[(size_t)fr * 768 + dd];
    }
    xt[idx] = v;
}

// ---------------- layernorm (row = 768) ----------------
__global__ void ln_k(const float* __restrict__ x, const float* __restrict__ sc,
                     const float* __restrict__ bi, float* __restrict__ y) {
    int row = blockIdx.x, tid = threadIdx.x;
    const float* xr = x + (size_t)row * DQ;
    float r0 = xr[tid], r1 = xr[tid + 256], r2 = xr[tid + 512];
    float mean = block_red(r0 + r1 + r2, 0) * (1.f / 768.f);
    float d0 = r0 - mean, d1 = r1 - mean, d2 = r2 - mean;
    float var = block_red(d0 * d0 + d1 * d1 + d2 * d2, 0) * (1.f / 768.f);
    float inv = rsqrtf(var + EPSQ);
    float* yr = y + (size_t)row * DQ;
    yr[tid]       = d0 * inv * sc[tid]       + bi[tid];
    yr[tid + 256] = d1 * inv * sc[tid + 256] + bi[tid + 256];
    yr[tid + 512] = d2 * inv * sc[tid + 512] + bi[tid + 512];
}

__global__ void final_ln_k(const float* __restrict__ xt, const float* __restrict__ sc,
                           const float* __restrict__ bi, float* __restrict__ out) {
    int b = blockIdx.x, tid = threadIdx.x;
    const float* xr = xt + (size_t)(b * SQ) * DQ;
    float r0 = xr[tid], r1 = xr[tid + 256], r2 = xr[tid + 512];
    float mean = block_red(r0 + r1 + r2, 0) * (1.f / 768.f);
    float d0 = r0 - mean, d1 = r1 - mean, d2 = r2 - mean;
    float var = block_red(d0 * d0 + d1 * d1 + d2 * d2, 0) * (1.f / 768.f);
    float inv = rsqrtf(var + EPSQ);
    float* yr = out + (size_t)b * DQ;
    yr[tid]       = d0 * inv * sc[tid]       + bi[tid];
    yr[tid + 256] = d1 * inv * sc[tid + 256] + bi[tid + 256];
    yr[tid + 512] = d2 * inv * sc[tid + 512] + bi[tid + 512];
}

// ============== fp16 2-term tensor-core GEMM (R2 skeleton) ==============
// C[M,N] = A[M,K] @ W[N,K]^T (+bias)(+res)(+gelu)
// A ~ Ah+Al (fp16 pair), W ~ Wh (fp16); C = Ah*Wh + Al*Wh, fp32 acc.
// Block 128x128x32, 256 thr (8 warps, 2x4), warp tile 64x32, mma m16n8k16.

#define GLD 36                                   // smem row stride (fp16 elems)
#define SARR (128*GLD)                           // one array (elems)
#define SSTG (3*SARR)                            // one stage (Ah,Al,Wh)
#define GEMM_SMEM (2*SSTG*2)                     // bytes = 55296

__device__ __forceinline__ uint32_t f2h2(float x0, float x1) {
    __half2 h = __floats2half2_rn(x0, x1);
    return *reinterpret_cast<uint32_t*>(&h);
}

__device__ __forceinline__ void mma16816(float* c,
        uint32_t a0, uint32_t a1, uint32_t a2, uint32_t a3,
        uint32_t b0, uint32_t b1) {
    asm volatile(
        "mma.sync.aligned.m16n8k16.row.col.f32.f16.f16.f32 "
        "{%0,%1,%2,%3}, {%4,%5,%6,%7}, {%8,%9}, {%0,%1,%2,%3};\n"
        : "+f"(c[0]), "+f"(c[1]), "+f"(c[2]), "+f"(c[3])
        : "r"(a0), "r"(a1), "r"(a2), "r"(a3), "r"(b0), "r"(b1));
}

// A: store hi + lo fp16
__device__ __forceinline__ void cvt_storeA(__half* hi, __half* lo,
                                           int row, int col, float4 v) {
    __half h0 = __float2half_rn(v.x), h1 = __float2half_rn(v.y);
    __half h2 = __float2half_rn(v.z), h3 = __float2half_rn(v.w);
    uint32_t* ph = (uint32_t*)&hi[row * GLD + col];
    uint32_t* pl = (uint32_t*)&lo[row * GLD + col];
    __half2 p0; p0.x = h0; p0.y = h1;
    __half2 p1; p1.x = h2; p1.y = h3;
    ph[0] = *(uint32_t*)&p0; ph[1] = *(uint32_t*)&p1;
    pl[0] = f2h2(v.x - __half2float(h0), v.y - __half2float(h1));
    pl[1] = f2h2(v.z - __half2float(h2), v.w - __half2float(h3));
}

// W: hi only
__device__ __forceinline__ void cvt_storeB(__half* hi, int row, int col, float4 v) {
    uint32_t* ph = (uint32_t*)&hi[row * GLD + col];
    ph[0] = f2h2(v.x, v.y);
    ph[1] = f2h2(v.z, v.w);
}

template<int ACT>
__global__ void __launch_bounds__(256, 1) gemm_k(
    const float* __restrict__ A, const float* __restrict__ W,
    const float* __restrict__ bias, const float* __restrict__ res,
    float* __restrict__ C, int M, int N, int K) {
    extern __shared__ __half smem[];

    int tid = threadIdx.x;
    int lane = tid & 31, w = tid >> 5;
    int warpM = w >> 2, warpN = w & 3;   // 2 x 4
    int g = lane >> 2, q = lane & 3;
    int bm = blockIdx.y * 128, bn = blockIdx.x * 128;

    int lrow = tid >> 3;                 // 0..31
    int lcol = (tid & 7) * 4;            // 0..28

    float acc[4][4][4];
    #pragma unroll
    for (int i = 0; i < 4; i++)
        #pragma unroll
        for (int j = 0; j < 4; j++)
            #pragma unroll
            for (int c = 0; c < 4; c++) acc[i][j][c] = 0.f;

    const int iters = K >> 5;            // K/32
    float4 aReg[4], bReg[4];

    // prologue: load tile 0
    #pragma unroll
    for (int u = 0; u < 4; u++) {
        int row = u * 32 + lrow;
        int gm = bm + row;
        aReg[u] = (gm < M) ? *(const float4*)(A + (size_t)gm * K + lcol)
                           : make_float4(0.f, 0.f, 0.f, 0.f);
        bReg[u] = *(const float4*)(W + (size_t)(bn + row) * K + lcol);
    }
    {
        __half* Ah = smem;           __half* Al = smem + SARR;
        __half* Bh = smem + 2 * SARR;
        #pragma unroll
        for (int u = 0; u < 4; u++) {
            int row = u * 32 + lrow;
            cvt_storeA(Ah, Al, row, lcol, aReg[u]);
            cvt_storeB(Bh, row, lcol, bReg[u]);
        }
    }
    __syncthreads();

    for (int iter = 0; iter < iters; iter++) {
        int cur = iter & 1, nxt = cur ^ 1;
        bool hasNext = (iter + 1) < iters;
        if (hasNext) {
            int k0 = (iter + 1) << 5;
            #pragma unroll
            for (int u = 0; u < 4; u++) {
                int row = u * 32 + lrow;
                int gm = bm + row;
                aReg[u] = (gm < M) ? *(const float4*)(A + (size_t)gm * K + k0 + lcol)
                                   : make_float4(0.f, 0.f, 0.f, 0.f);
                bReg[u] = *(const float4*)(W + (size_t)(bn + row) * K + k0 + lcol);
            }
        }
        const __half* Ah = smem + cur * SSTG;
        const __half* Al = Ah + SARR;
        const __half* Bh = Ah + 2 * SARR;

        #pragma unroll
        for (int kk = 0; kk < 2; kk++) {
            int c0 = kk * 16 + q * 2;
            uint32_t ah[4][4], al[4][4], bh[4][2];
            #pragma unroll
            for (int i = 0; i < 4; i++) {
                int r0 = warpM * 64 + i * 16 + g;
                const __half* p0 = Ah + r0 * GLD + c0;
                const __half* p1 = Ah + (r0 + 8) * GLD + c0;
                ah[i][0] = *(const uint32_t*)(p0);
                ah[i][1] = *(const uint32_t*)(p1);
                ah[i][2] = *(const uint32_t*)(p0 + 8);
                ah[i][3] = *(const uint32_t*)(p1 + 8);
                const __half* q0 = Al + r0 * GLD + c0;
                const __half* q1 = Al + (r0 + 8) * GLD + c0;
                al[i][0] = *(const uint32_t*)(q0);
                al[i][1] = *(const uint32_t*)(q1);
                al[i][2] = *(const uint32_t*)(q0 + 8);
                al[i][3] = *(const uint32_t*)(q1 + 8);
            }
            #pragma unroll
            for (int j = 0; j < 4; j++) {
                int nr = warpN * 32 + j * 8 + g;
                const __half* p = Bh + nr * GLD + c0;
                bh[j][0] = *(const uint32_t*)(p);
                bh[j][1] = *(const uint32_t*)(p + 8);
            }
            #pragma unroll
            for (int i = 0; i < 4; i++)
                #pragma unroll
                for (int j = 0; j < 4; j++) {
                    mma16816(acc[i][j], ah[i][0], ah[i][1], ah[i][2], ah[i][3],
                             bh[j][0], bh[j][1]);
                    mma16816(acc[i][j], al[i][0], al[i][1], al[i][2], al[i][3],
                             bh[j][0], bh[j][1]);
                }
        }

        if (hasNext) {
            __half* Ah2 = smem + nxt * SSTG;
            __half* Al2 = Ah2 + SARR;
            __half* Bh2 = Ah2 + 2 * SARR;
            #pragma unroll
            for (int u = 0; u < 4; u++) {
                int row = u * 32 + lrow;
                cvt_storeA(Ah2, Al2, row, lcol, aReg[u]);
                cvt_storeB(Bh2, row, lcol, bReg[u]);
            }
        }
        __syncthreads();
    }

    // epilogue
    #pragma unroll
    for (int i = 0; i < 4; i++) {
        int m0 = bm + warpM * 64 + i * 16 + g;
        #pragma unroll
        for (int j = 0; j < 4; j++) {
            int n0 = bn + warpN * 32 + j * 8 + q * 2;
            float bx = bias ? bias[n0] : 0.f;
            float by = bias ? bias[n0 + 1] : 0.f;
            #pragma unroll
            for (int half = 0; half < 2; half++) {
                int m = m0 + half * 8;
                if (m >= M) continue;
                float v0 = acc[i][j][half * 2 + 0] + bx;
                float v1 = acc[i][j][half * 2 + 1] + by;
                if (res) {
                    const float* rp = res + (size_t)m * N + n0;
                    v0 += rp[0]; v1 += rp[1];
                }
                if (ACT == 1) {
                    v0 = 0.5f * v0 * (1.f + erff(v0 * 0.70710678118654752f));
                    v1 = 0.5f * v1 * (1.f + erff(v1 * 0.70710678118654752f));
                }
                float2* cp = (float2*)(C + (size_t)m * N + n0);
                *cp = make_float2(v0, v1);
            }
        }
    }
}

// ---------------- cls-row attention ----------------
__global__ void cls_attn_k(const float* __restrict__ qkv, float* __restrict__ outp) {
    __shared__ float sc[SQ];
    __shared__ float qv[64];
    __shared__ float op[256];
    int bh = blockIdx.x, b = bh / 12, h = bh % 12;
    int tid = threadIdx.x;
    size_t base = (size_t)(b * SQ) * 2304 + (size_t)h * 64;
    if (tid < 64) qv[tid] = qkv[base + tid] * SCALEQ;
    __syncthreads();
    float lmax = -1e30f;
    for (int s = tid; s < SQ; s += 256) {
        const float* kp = qkv + (size_t)(b * SQ + s) * 2304 + 768 + h * 64;
        float d = 0.f;
        #pragma unroll
        for (int i = 0; i < 64; i++) d += qv[i] * kp[i];
        sc[s] = d; lmax = fmaxf(lmax, d);
    }
    float mx = block_red(lmax, 1);
    float lsum = 0.f;
    for (int s = tid; s < SQ; s += 256) {
        float e = expf(sc[s] - mx);
        sc[s] = e; lsum += e;
    }
    float den = block_red(lsum, 0);
    __syncthreads();
    int part = tid >> 6, d = tid & 63;
    float acc = 0.f;
    for (int s = part; s < SQ; s += 4)
        acc += sc[s] * qkv[(size_t)(b * SQ + s) * 2304 + 1536 + h * 64 + d];
    op[tid] = acc;
    __syncthreads();
    if (tid < 64) {
        float t = op[tid] + op[tid + 64] + op[tid + 128] + op[tid + 192];
        outp[(size_t)(b * SQ) * 768 + h * 64 + tid] = t / den;
    }
}

// ---------------- space attention ----------------
#define SPACE_SMEM ((197*65*2 + 8*197 + 8*64) * 4)
__global__ void space_attn_k(const float* __restrict__ qkv, float* __restrict__ outp) {
    extern __shared__ float sm[];
    float* Ks = sm;
    float* Vs = Ks + 197 * 65;
    float* pb = Vs + 197 * 65;
    float* qb = pb + 8 * 197;
    int blk = blockIdx.x;
    int fr = blk % 8, h = (blk / 8) % 12, b = blk / 96;
    int tid = threadIdx.x, lane = tid & 31, w = tid >> 5;
    for (int idx = tid; idx < 197 * 64; idx += 256) {
        int kk = idx >> 6, d = idx & 63;
        int s = kk ? (1 + fr * 196 + kk - 1) : 0;
        size_t o = (size_t)(b * SQ + s) * 2304 + h * 64;
        Ks[kk * 65 + d] = qkv[o + 768 + d];
        Vs[kk * 65 + d] = qkv[o + 1536 + d];
    }
    __syncthreads();
    for (int qi = w; qi < 196; qi += 8) {
        int sq = 1 + fr * 196 + qi;
        size_t oq = (size_t)(b * SQ + sq) * 2304 + h * 64;
        qb[w * 64 + lane]      = qkv[oq + lane] * SCALEQ;
        qb[w * 64 + lane + 32] = qkv[oq + lane + 32] * SCALEQ;
        __syncwarp();
        float ls[7];
        float lmax = -1e30f;
        int cnt = 0;
        for (int kk = lane; kk < 197; kk += 32) {
            float s = 0.f;
            #pragma unroll
            for (int d = 0; d < 64; d++) s += qb[w * 64 + d] * Ks[kk * 65 + d];
            ls[cnt++] = s; lmax = fmaxf(lmax, s);
        }
        #pragma unroll
        for (int o = 16; o; o >>= 1) lmax = fmaxf(lmax, __shfl_xor_sync(0xffffffffu, lmax, o));
        float lsum = 0.f; cnt = 0;
        for (int kk = lane; kk < 197; kk += 32) {
            float e = expf(ls[cnt++] - lmax);
            pb[w * 197 + kk] = e; lsum += e;
        }
        #pragma unroll
        for (int o = 16; o; o >>= 1) lsum += __shfl_xor_sync(0xffffffffu, lsum, o);
        float inv = 1.f / lsum;
        __syncwarp();
        float a0 = 0.f, a1 = 0.f;
        for (int kk = 0; kk < 197; kk++) {
            float p = pb[w * 197 + kk];
            a0 += p * Vs[kk * 65 + lane];
            a1 += p * Vs[kk * 65 + lane + 32];
        }
        size_t oo = (size_t)(b * SQ + sq) * 768 + h * 64;
        outp[oo + lane]      = a0 * inv;
        outp[oo + lane + 32] = a1 * inv;
        __syncwarp();
    }
}

// ---------------- time attention ----------------
__global__ void time_attn_k(const float* __restrict__ qkv, float* __restrict__ outp) {
    int g = blockIdx.x * 8 + (threadIdx.x >> 5);
    int lane = threadIdx.x & 31;
    if (g >= 48 * 196) return;
    int bh = g / 196, pos = g % 196;
    int b = bh / 12, h = bh % 12;
    float K0[9], K1[9], V0[9], V1[9];
    #pragma unroll
    for (int kk = 0; kk < 9; kk++) {
        int s = kk ? (1 + (kk - 1) * 196 + pos) : 0;
        size_t o = (size_t)(b * SQ + s) * 2304 + h * 64;
        K0[kk] = qkv[o + 768 + lane];  K1[kk] = qkv[o + 768 + lane + 32];
        V0[kk] = qkv[o + 1536 + lane]; V1[kk] = qkv[o + 1536 + lane + 32];
    }
    for (int fq = 0; fq < 8; fq++) {
        int sq = 1 + fq * 196 + pos;
        size_t oq = (size_t)(b * SQ + sq) * 2304 + h * 64;
        float q0 = qkv[oq + lane] * SCALEQ, q1 = qkv[oq + lane + 32] * SCALEQ;
        float sc[9];
        #pragma unroll
        for (int kk = 0; kk < 9; kk++) {
            float p = q0 * K0[kk] + q1 * K1[kk];
            #pragma unroll
            for (int o = 16; o; o >>= 1) p += __shfl_xor_sync(0xffffffffu, p, o);
            sc[kk] = p;
        }
        float mx = sc[0];
        #pragma unroll
        for (int kk = 1; kk < 9; kk++) mx = fmaxf(mx, sc[kk]);
        float den = 0.f;
        #pragma unroll
        for (int kk = 0; kk < 9; kk++) { sc[kk] = expf(sc[kk] - mx); den += sc[kk]; }
        float inv = 1.f / den;
        float a0 = 0.f, a1 = 0.f;
        #pragma unroll
        for (int kk = 0; kk < 9; kk++) { a0 += sc[kk] * V0[kk]; a1 += sc[kk] * V1[kk]; }
        size_t oo = (size_t)(b * SQ + sq) * 768 + h * 64;
        outp[oo + lane]      = a0 * inv;
        outp[oo + lane + 32] = a1 * inv;
    }
}

// ---------------- host orchestration ----------------
static void gemm(const float* A, const float* W, const float* bias, const float* res,
                 float* C, int M, int N, int K, int act) {
    dim3 g(N / 128, (M + 127) / 128);
    if (act) gemm_k<1><<<g, 256, GEMM_SMEM>>>(A, W, bias, res, C, M, N, K);
    else     gemm_k<0><<<g, 256, GEMM_SMEM>>>(A, W, bias, res, C, M, N, K);
}

extern "C" void kernel_launch(void* const* d_in, const int* in_sizes, int n_in,
                              void* d_out, int out_size) {
    const float* x       = (const float*)d_in[0];
    const float* patch_w = (const float*)d_in[1];
    const float* patch_b = (const float*)d_in[2];
    const float* cls_tok = (const float*)d_in[3];
    const float* pos     = (const float*)d_in[4];
    const float* temp    = (const float*)d_in[5];
    const float* n1s = (const float*)d_in[6],  *n1b = (const float*)d_in[7];
    const float* n2s = (const float*)d_in[8],  *n2b = (const float*)d_in[9];
    const float* n3s = (const float*)d_in[10], *n3b = (const float*)d_in[11];
    const float* aqw = (const float*)d_in[12], *aqb = (const float*)d_in[13];
    const float* apw = (const float*)d_in[14], *apb = (const float*)d_in[15];
    const float* tqw = (const float*)d_in[16], *tqb = (const float*)d_in[17];
    const float* tpw = (const float*)d_in[18], *tpb = (const float*)d_in[19];
    const float* f1w = (const float*)d_in[20], *f1b = (const float*)d_in[21];
    const float* f2w = (const float*)d_in[22], *f2b = (const float*)d_in[23];
    const float* nfs = (const float*)d_in[24], *nfb = (const float*)d_in[25];
    float* out = (float*)d_out;

    float *xt, *ln, *qkv, *attn, *res, *hid;
    cudaGetSymbolAddress((void**)&xt,   g_xt);
    cudaGetSymbolAddress((void**)&ln,   g_ln);
    cudaGetSymbolAddress((void**)&qkv,  g_qkv);
    cudaGetSymbolAddress((void**)&attn, g_attn);
    cudaGetSymbolAddress((void**)&res,  g_res);
    cudaGetSymbolAddress((void**)&hid,  g_hid);

    cudaFuncSetAttribute(space_attn_k, cudaFuncAttributeMaxDynamicSharedMemorySize, SPACE_SMEM);
    cudaFuncSetAttribute(gemm_k<0>, cudaFuncAttributeMaxDynamicSharedMemorySize, GEMM_SMEM);
    cudaFuncSetAttribute(gemm_k<1>, cudaFuncAttributeMaxDynamicSharedMemorySize, GEMM_SMEM);

    // ---- patch embedding ----
    im2col_k<<<(6272 * 768 + 255) / 256, 256>>>(x, hid);
    gemm(hid, patch_w, nullptr, nullptr, ln, 6272, 768, 768, 0);
    assemble_k<<<(TQ * DQ + 255) / 256, 256>>>(ln, patch_b, cls_tok, pos, temp, xt);

    for (int l = 0; l < LQ; l++) {
        // ---- time attention ----
        ln_k<<<TQ, 256>>>(xt, n3s + (size_t)l * DQ, n3b + (size_t)l * DQ, ln);
        gemm(ln, tqw + (size_t)l * 3 * DQ * DQ, tqb + (size_t)l * 3 * DQ, nullptr,
             qkv, TQ, 3 * DQ, DQ, 0);
        cls_attn_k<<<48, 256>>>(qkv, attn);
        time_attn_k<<<1176, 256>>>(qkv, attn);
        gemm(attn, tpw + (size_t)l * DQ * DQ, tpb + (size_t)l * DQ, xt,
             res, TQ, DQ, DQ, 0);                          // time_res = xt + t_out
        // ---- space attention ----
        ln_k<<<TQ, 256>>>(res, n1s + (size_t)l * DQ, n1b + (size_t)l * DQ, ln);
        gemm(ln, aqw + (size_t)l * 3 * DQ * DQ, aqb + (size_t)l * 3 * DQ, nullptr,
             qkv, TQ, 3 * DQ, DQ, 0);
        cls_attn_k<<<48, 256>>>(qkv, attn);
        space_attn_k<<<384, 256, SPACE_SMEM>>>(qkv, attn);
        gemm(attn, apw + (size_t)l * DQ * DQ, apb + (size_t)l * DQ, xt,
             res, TQ, DQ, DQ, 0);                          // space_res = xt + s_out
        // ---- MLP ----
        ln_k<<<TQ, 256>>>(res, n2s + (size_t)l * DQ, n2b + (size_t)l * DQ, ln);
        gemm(ln, f1w + (size_t)l * HIDQ * DQ, f1b + (size_t)l * HIDQ, nullptr,
             hid, TQ, HIDQ, DQ, 1);                        // GELU
        gemm(hid, f2w + (size_t)l * DQ * HIDQ, f2b + (size_t)l * DQ, res,
             xt, TQ, DQ, HIDQ, 0);                         // xt = space_res + mlp
    }

    final_ln_k<<<BQ, 256>>>(xt, nfs, nfb, out);
}